// round 13
// baseline (speedup 1.0000x reference)
#include <cuda_runtime.h>
#include <cstdint>

#define D 128
#define BM 64
#define BK 32
#define NTHR 128
#define LDA 36     // smem A leading dim (pad: (36r+c)%32 = (4r+c)%32 -> conflict-free frags)
#define LDH 132    // smem H leading dim (132%32==4, same property)
#define LDB 136    // smem B leading dim ((136k+n)%32 = (8k+n)%32 -> conflict-free frags)

#define MAX_NODES 100000

// scatter-sum scratch (51.2 MB) — __device__ global per allocation rules
__device__ __align__(16) float g_agg[(size_t)MAX_NODES * D];

struct Smem {
    float A[2][BM * LDA];   // 18432 B
    float B[2][BK * LDB];   // 34816 B
    float Hh[BM * LDH];     // 33792 B
    int   sidx[BM];
    int   ridx[BM];
    float bias1[D];
    float bias2[D];
};  // ~88.5 KB -> 2 blocks/SM

__device__ __forceinline__ float to_tf32(float x) {
    uint32_t u;
    asm("cvt.rna.tf32.f32 %0, %1;" : "=r"(u) : "f"(x));
    return __uint_as_float(u);
}

__device__ __forceinline__ void mma_tf32(float d[4], const uint32_t a[4], const uint32_t b[2]) {
    asm volatile(
        "mma.sync.aligned.m16n8k8.row.col.f32.tf32.tf32.f32 "
        "{%0,%1,%2,%3}, {%4,%5,%6,%7}, {%8,%9}, {%0,%1,%2,%3};"
        : "+f"(d[0]), "+f"(d[1]), "+f"(d[2]), "+f"(d[3])
        : "r"(a[0]), "r"(a[1]), "r"(a[2]), "r"(a[3]), "r"(b[0]), "r"(b[1]));
}

// One BK=32 K-chunk of mma for a 64x128 block tile. Warp tile = 32(m) x 64(n).
template <int LDA_T>
__device__ __forceinline__ void mma_chunk(const float* sA, const float* sB,
                                          int warp_m, int warp_n, int lane,
                                          float acc[2][8][4]) {
    const int g = lane >> 2, t = lane & 3;
    #pragma unroll
    for (int ks = 0; ks < 4; ++ks) {
        const int k = ks * 8;
        uint32_t a[2][4];
        #pragma unroll
        for (int mf = 0; mf < 2; ++mf) {
            const int r0 = warp_m * 32 + mf * 16 + g;
            a[mf][0] = __float_as_uint(sA[r0 * LDA_T + k + t]);
            a[mf][1] = __float_as_uint(sA[(r0 + 8) * LDA_T + k + t]);
            a[mf][2] = __float_as_uint(sA[r0 * LDA_T + k + t + 4]);
            a[mf][3] = __float_as_uint(sA[(r0 + 8) * LDA_T + k + t + 4]);
        }
        #pragma unroll
        for (int nf = 0; nf < 8; ++nf) {
            const int col = warp_n * 64 + nf * 8 + g;
            uint32_t b[2];
            b[0] = __float_as_uint(sB[(k + t) * LDB + col]);
            b[1] = __float_as_uint(sB[(k + t + 4) * LDB + col]);
            mma_tf32(acc[0][nf], a[0], b);
            mma_tf32(acc[1][nf], a[1], b);
        }
    }
}

// ---- global -> reg -> (rna tf32) -> smem staging ----

__device__ __forceinline__ void ldg_B(float4 r[8], const float* __restrict__ W, int k0) {
    #pragma unroll
    for (int i = 0; i < 8; ++i) {
        const int idx = threadIdx.x + i * NTHR;       // 0..1023 over 32x32 float4
        const int kr = idx >> 5, c4 = idx & 31;
        r[i] = *reinterpret_cast<const float4*>(W + (size_t)(k0 + kr) * D + c4 * 4);
    }
}

__device__ __forceinline__ void sts_B(float* sB, const float4 r[8]) {
    #pragma unroll
    for (int i = 0; i < 8; ++i) {
        const int idx = threadIdx.x + i * NTHR;
        const int kr = idx >> 5, c4 = idx & 31;
        float4 v = r[i];
        v.x = to_tf32(v.x); v.y = to_tf32(v.y); v.z = to_tf32(v.z); v.w = to_tf32(v.w);
        *reinterpret_cast<float4*>(sB + kr * LDB + c4 * 4) = v;
    }
}

__device__ __forceinline__ void sts_A(float* sA, const float4 r[4]) {
    #pragma unroll
    for (int i = 0; i < 4; ++i) {
        const int idx = threadIdx.x + i * NTHR;       // 0..511 over 64x8 float4
        const int row = idx >> 3, c4 = idx & 7;
        float4 v = r[i];
        v.x = to_tf32(v.x); v.y = to_tf32(v.y); v.z = to_tf32(v.z); v.w = to_tf32(v.w);
        *reinterpret_cast<float4*>(sA + row * LDA + c4 * 4) = v;
    }
}

__device__ __forceinline__ void ldg_A_edge(float4 r[4],
                                           const float* __restrict__ nodes,
                                           const float* __restrict__ edges,
                                           const int* sidx, const int* ridx,
                                           long e0, long E, int chunk) {
    #pragma unroll
    for (int i = 0; i < 4; ++i) {
        const int idx = threadIdx.x + i * NTHR;
        const int row = idx >> 3, c4 = idx & 7;
        const float* src;
        if (chunk < 4)       src = nodes + (size_t)sidx[row] * D + chunk * 32;
        else if (chunk < 8)  src = nodes + (size_t)ridx[row] * D + (chunk - 4) * 32;
        else                 src = edges + (size_t)(e0 + row) * D + (chunk - 8) * 32;
        r[i] = (e0 + row < E) ? *reinterpret_cast<const float4*>(src + c4 * 4)
                              : make_float4(0.f, 0.f, 0.f, 0.f);
    }
}

__device__ __forceinline__ void ldg_A_node(float4 r[4],
                                           const float* __restrict__ nodes,
                                           long n0, long N, int chunk) {
    #pragma unroll
    for (int i = 0; i < 4; ++i) {
        const int idx = threadIdx.x + i * NTHR;
        const int row = idx >> 3, c4 = idx & 7;
        const long n = n0 + row;
        const float* src = (chunk < 4) ? nodes + (size_t)n * D + chunk * 32
                                       : g_agg + (size_t)n * D + (chunk - 4) * 32;
        r[i] = (n < N) ? *reinterpret_cast<const float4*>(src + c4 * 4)
                       : make_float4(0.f, 0.f, 0.f, 0.f);
    }
}

__device__ __forceinline__ void zero_acc(float acc[2][8][4]) {
    #pragma unroll
    for (int mf = 0; mf < 2; ++mf)
        #pragma unroll
        for (int nf = 0; nf < 8; ++nf)
            #pragma unroll
            for (int i = 0; i < 4; ++i) acc[mf][nf][i] = 0.f;
}

// Store acc(+bias1), relu, rna -> Hh; or acc(+bias2) -> Hh (no relu).
__device__ __forceinline__ void acc_to_H(float* Hh, float acc[2][8][4],
                                         const float* bias, int warp_m, int warp_n,
                                         int lane, bool relu_rna) {
    const int g = lane >> 2, t = lane & 3;
    #pragma unroll
    for (int mf = 0; mf < 2; ++mf) {
        const int r0 = warp_m * 32 + mf * 16 + g;
        #pragma unroll
        for (int nf = 0; nf < 8; ++nf) {
            const int col = warp_n * 64 + nf * 8 + 2 * t;
            float2 v0, v1;
            v0.x = acc[mf][nf][0] + bias[col];
            v0.y = acc[mf][nf][1] + bias[col + 1];
            v1.x = acc[mf][nf][2] + bias[col];
            v1.y = acc[mf][nf][3] + bias[col + 1];
            if (relu_rna) {
                v0.x = to_tf32(fmaxf(v0.x, 0.f)); v0.y = to_tf32(fmaxf(v0.y, 0.f));
                v1.x = to_tf32(fmaxf(v1.x, 0.f)); v1.y = to_tf32(fmaxf(v1.y, 0.f));
            }
            *reinterpret_cast<float2*>(&Hh[r0 * LDH + col]) = v0;
            *reinterpret_cast<float2*>(&Hh[(r0 + 8) * LDH + col]) = v1;
        }
    }
}

// =================== edge kernel ===================
__global__ void __launch_bounds__(NTHR, 2)
edge_kernel(const float* __restrict__ nodes, const float* __restrict__ edges,
            const int* __restrict__ senders, const int* __restrict__ receivers,
            const float* __restrict__ We1, const float* __restrict__ be1,
            const float* __restrict__ We2, const float* __restrict__ be2,
            float* __restrict__ out_edges, long E)
{
    extern __shared__ char smem_raw[];
    Smem& S = *reinterpret_cast<Smem*>(smem_raw);
    const long e0 = (long)blockIdx.x * BM;
    const int tid = threadIdx.x, lane = tid & 31;
    const int warp_m = (tid >> 5) & 1, warp_n = tid >> 6;

    if (tid < BM) { const long e = e0 + tid; S.sidx[tid] = (e < E) ? senders[e] : 0; }
    else          { const int r = tid - BM; const long e = e0 + r; S.ridx[r] = (e < E) ? receivers[e] : 0; }
    S.bias1[tid] = be1[tid];
    S.bias2[tid] = be2[tid];
    __syncthreads();

    float acc[2][8][4];
    zero_acc(acc);

    float4 ra[4], rb[8];

    // ---- GEMM1: [64,384] x [384,128], 12 K-chunks, double buffered ----
    ldg_A_edge(ra, nodes, edges, S.sidx, S.ridx, e0, E, 0);
    ldg_B(rb, We1, 0);
    sts_A(S.A[0], ra); sts_B(S.B[0], rb);
    __syncthreads();
    #pragma unroll 1
    for (int c = 0; c < 12; ++c) {
        const int cur = c & 1;
        if (c + 1 < 12) {
            ldg_A_edge(ra, nodes, edges, S.sidx, S.ridx, e0, E, c + 1);
            ldg_B(rb, We1, (c + 1) * BK);
        }
        mma_chunk<LDA>(S.A[cur], S.B[cur], warp_m, warp_n, lane, acc);
        if (c + 1 < 12) { sts_A(S.A[cur ^ 1], ra); sts_B(S.B[cur ^ 1], rb); }
        __syncthreads();
    }

    // h = rna(relu(acc + b1)) -> Hh ; prefetch W2 chunk0
    ldg_B(rb, We2, 0);
    acc_to_H(S.Hh, acc, S.bias1, warp_m, warp_n, lane, true);
    zero_acc(acc);
    sts_B(S.B[0], rb);
    __syncthreads();

    // ---- GEMM2: [64,128] x [128,128], 4 K-chunks ----
    #pragma unroll 1
    for (int c = 0; c < 4; ++c) {
        const int cur = c & 1;
        if (c + 1 < 4) ldg_B(rb, We2, (c + 1) * BK);
        mma_chunk<LDH>(S.Hh + c * BK, S.B[cur], warp_m, warp_n, lane, acc);
        if (c + 1 < 4) sts_B(S.B[cur ^ 1], rb);
        __syncthreads();
    }

    // y = acc + b2 -> Hh
    acc_to_H(S.Hh, acc, S.bias2, warp_m, warp_n, lane, false);
    __syncthreads();

    // new_edges = edges + y ; agg[recv] += y (vectorized red)
    #pragma unroll 1
    for (int i = 0; i < 16; ++i) {
        const int idx = tid + i * NTHR;            // 0..2047 over 64x32 float4
        const int row = idx >> 5, c4 = idx & 31;
        const long e = e0 + row;
        if (e < E) {
            const float4 ef = *reinterpret_cast<const float4*>(edges + (size_t)e * D + c4 * 4);
            const float4 y  = *reinterpret_cast<const float4*>(&S.Hh[row * LDH + c4 * 4]);
            float4 o;
            o.x = ef.x + y.x; o.y = ef.y + y.y; o.z = ef.z + y.z; o.w = ef.w + y.w;
            *reinterpret_cast<float4*>(out_edges + (size_t)e * D + c4 * 4) = o;
            float* dst = g_agg + (size_t)S.ridx[row] * D + c4 * 4;
            asm volatile("red.global.add.v4.f32 [%0], {%1,%2,%3,%4};"
                         :: "l"(dst), "f"(y.x), "f"(y.y), "f"(y.z), "f"(y.w) : "memory");
        }
    }
}

// =================== node kernel ===================
__global__ void __launch_bounds__(NTHR, 2)
node_kernel(const float* __restrict__ nodes,
            const float* __restrict__ Wn1, const float* __restrict__ bn1,
            const float* __restrict__ Wn2, const float* __restrict__ bn2,
            float* __restrict__ out_nodes, long N)
{
    extern __shared__ char smem_raw[];
    Smem& S = *reinterpret_cast<Smem*>(smem_raw);
    const long n0 = (long)blockIdx.x * BM;
    const int tid = threadIdx.x, lane = tid & 31;
    const int warp_m = (tid >> 5) & 1, warp_n = tid >> 6;

    S.bias1[tid] = bn1[tid];
    S.bias2[tid] = bn2[tid];
    __syncthreads();

    float acc[2][8][4];
    zero_acc(acc);

    float4 ra[4], rb[8];

    // ---- GEMM1: [64,256] x [256,128], 8 K-chunks ----
    ldg_A_node(ra, nodes, n0, N, 0);
    ldg_B(rb, Wn1, 0);
    sts_A(S.A[0], ra); sts_B(S.B[0], rb);
    __syncthreads();
    #pragma unroll 1
    for (int c = 0; c < 8; ++c) {
        const int cur = c & 1;
        if (c + 1 < 8) {
            ldg_A_node(ra, nodes, n0, N, c + 1);
            ldg_B(rb, Wn1, (c + 1) * BK);
        }
        mma_chunk<LDA>(S.A[cur], S.B[cur], warp_m, warp_n, lane, acc);
        if (c + 1 < 8) { sts_A(S.A[cur ^ 1], ra); sts_B(S.B[cur ^ 1], rb); }
        __syncthreads();
    }

    ldg_B(rb, Wn2, 0);
    acc_to_H(S.Hh, acc, S.bias1, warp_m, warp_n, lane, true);
    zero_acc(acc);
    sts_B(S.B[0], rb);
    __syncthreads();

    // ---- GEMM2: [64,128] x [128,128] ----
    #pragma unroll 1
    for (int c = 0; c < 4; ++c) {
        const int cur = c & 1;
        if (c + 1 < 4) ldg_B(rb, Wn2, (c + 1) * BK);
        mma_chunk<LDH>(S.Hh + c * BK, S.B[cur], warp_m, warp_n, lane, acc);
        if (c + 1 < 4) sts_B(S.B[cur ^ 1], rb);
        __syncthreads();
    }

    acc_to_H(S.Hh, acc, S.bias2, warp_m, warp_n, lane, false);
    __syncthreads();

    // new_nodes = nodes + y
    #pragma unroll 1
    for (int i = 0; i < 16; ++i) {
        const int idx = tid + i * NTHR;
        const int row = idx >> 5, c4 = idx & 31;
        const long n = n0 + row;
        if (n < N) {
            const float4 nf = *reinterpret_cast<const float4*>(nodes + (size_t)n * D + c4 * 4);
            const float4 y  = *reinterpret_cast<const float4*>(&S.Hh[row * LDH + c4 * 4]);
            float4 o;
            o.x = nf.x + y.x; o.y = nf.y + y.y; o.z = nf.z + y.z; o.w = nf.w + y.w;
            *reinterpret_cast<float4*>(out_nodes + (size_t)n * D + c4 * 4) = o;
        }
    }
}

// =================== zero the scatter scratch ===================
__global__ void zero_agg_kernel(long n4) {
    float4* p = reinterpret_cast<float4*>(g_agg);
    long i = (long)blockIdx.x * blockDim.x + threadIdx.x;
    const long stride = (long)gridDim.x * blockDim.x;
    const float4 z = make_float4(0.f, 0.f, 0.f, 0.f);
    for (; i < n4; i += stride) p[i] = z;
}

extern "C" void kernel_launch(void* const* d_in, const int* in_sizes, int n_in,
                              void* d_out, int out_size) {
    const float* nodes     = (const float*)d_in[0];
    const float* edges     = (const float*)d_in[1];
    const int*   senders   = (const int*)d_in[2];
    const int*   receivers = (const int*)d_in[3];
    const float* We1 = (const float*)d_in[4];
    const float* be1 = (const float*)d_in[5];
    const float* We2 = (const float*)d_in[6];
    const float* be2 = (const float*)d_in[7];
    const float* Wn1 = (const float*)d_in[8];
    const float* bn1 = (const float*)d_in[9];
    const float* Wn2 = (const float*)d_in[10];
    const float* bn2 = (const float*)d_in[11];

    const long N = (long)in_sizes[0] / D;
    const long E = (long)in_sizes[2];

    float* out_nodes = (float*)d_out;               // [N, D] first
    float* out_edges = out_nodes + (size_t)N * D;   // then [E, D]

    const int smem = (int)sizeof(Smem);
    cudaFuncSetAttribute(edge_kernel, cudaFuncAttributeMaxDynamicSharedMemorySize, smem);
    cudaFuncSetAttribute(node_kernel, cudaFuncAttributeMaxDynamicSharedMemorySize, smem);

    zero_agg_kernel<<<2048, 256>>>(N * D / 4);
    edge_kernel<<<(int)((E + BM - 1) / BM), NTHR, smem>>>(
        nodes, edges, senders, receivers, We1, be1, We2, be2, out_edges, E);
    node_kernel<<<(int)((N + BM - 1) / BM), NTHR, smem>>>(
        nodes, Wn1, bn1, Wn2, bn2, out_nodes, N);
}

// round 14
// speedup vs baseline: 1.0092x; 1.0092x over previous
#include <cuda_runtime.h>
#include <cstdint>

#define D 128
#define BM 64
#define BK 32
#define NTHR 128
#define LDA 36     // smem A leading dim (pad: (36r+c)%32 = (4r+c)%32 -> conflict-free frags)
#define LDH 132    // smem H leading dim (132%32==4, same property)
#define LDB 136    // smem B leading dim ((136k+n)%32 = (8k+n)%32 -> conflict-free frags)

#define MAX_NODES 100000

// scatter-sum scratch (51.2 MB) — __device__ global per allocation rules
__device__ __align__(16) float g_agg[(size_t)MAX_NODES * D];

struct Smem {
    float A[2][BM * LDA];   // 18432 B
    float B[2][BK * LDB];   // 34816 B
    float Hh[BM * LDH];     // 33792 B
    int   sidx[BM];
    int   ridx[BM];
    float bias1[D];
    float bias2[D];
};  // ~88.5 KB -> 2 blocks/SM

__device__ __forceinline__ float to_tf32(float x) {
    uint32_t u;
    asm("cvt.rna.tf32.f32 %0, %1;" : "=r"(u) : "f"(x));
    return __uint_as_float(u);
}

__device__ __forceinline__ void mma_tf32(float d[4], const uint32_t a[4], const uint32_t b[2]) {
    asm volatile(
        "mma.sync.aligned.m16n8k8.row.col.f32.tf32.tf32.f32 "
        "{%0,%1,%2,%3}, {%4,%5,%6,%7}, {%8,%9}, {%0,%1,%2,%3};"
        : "+f"(d[0]), "+f"(d[1]), "+f"(d[2]), "+f"(d[3])
        : "r"(a[0]), "r"(a[1]), "r"(a[2]), "r"(a[3]), "r"(b[0]), "r"(b[1]));
}

// One BK=32 K-chunk of mma for a 64x128 block tile. Warp tile = 32(m) x 64(n).
template <int LDA_T>
__device__ __forceinline__ void mma_chunk(const float* sA, const float* sB,
                                          int warp_m, int warp_n, int lane,
                                          float acc[2][8][4]) {
    const int g = lane >> 2, t = lane & 3;
    #pragma unroll
    for (int ks = 0; ks < 4; ++ks) {
        const int k = ks * 8;
        uint32_t a[2][4];
        #pragma unroll
        for (int mf = 0; mf < 2; ++mf) {
            const int r0 = warp_m * 32 + mf * 16 + g;
            a[mf][0] = __float_as_uint(sA[r0 * LDA_T + k + t]);
            a[mf][1] = __float_as_uint(sA[(r0 + 8) * LDA_T + k + t]);
            a[mf][2] = __float_as_uint(sA[r0 * LDA_T + k + t + 4]);
            a[mf][3] = __float_as_uint(sA[(r0 + 8) * LDA_T + k + t + 4]);
        }
        #pragma unroll
        for (int nf = 0; nf < 8; ++nf) {
            const int col = warp_n * 64 + nf * 8 + g;
            uint32_t b[2];
            b[0] = __float_as_uint(sB[(k + t) * LDB + col]);
            b[1] = __float_as_uint(sB[(k + t + 4) * LDB + col]);
            mma_tf32(acc[0][nf], a[0], b);
            mma_tf32(acc[1][nf], a[1], b);
        }
    }
}

// ---- global -> reg -> (rna tf32) -> smem staging ----

__device__ __forceinline__ void ldg_B(float4 r[8], const float* __restrict__ W, int k0) {
    #pragma unroll
    for (int i = 0; i < 8; ++i) {
        const int idx = threadIdx.x + i * NTHR;       // 0..1023 over 32x32 float4
        const int kr = idx >> 5, c4 = idx & 31;
        r[i] = *reinterpret_cast<const float4*>(W + (size_t)(k0 + kr) * D + c4 * 4);
    }
}

__device__ __forceinline__ void sts_B(float* sB, const float4 r[8]) {
    #pragma unroll
    for (int i = 0; i < 8; ++i) {
        const int idx = threadIdx.x + i * NTHR;
        const int kr = idx >> 5, c4 = idx & 31;
        float4 v = r[i];
        v.x = to_tf32(v.x); v.y = to_tf32(v.y); v.z = to_tf32(v.z); v.w = to_tf32(v.w);
        *reinterpret_cast<float4*>(sB + kr * LDB + c4 * 4) = v;
    }
}

__device__ __forceinline__ void sts_A(float* sA, const float4 r[4]) {
    #pragma unroll
    for (int i = 0; i < 4; ++i) {
        const int idx = threadIdx.x + i * NTHR;       // 0..511 over 64x8 float4
        const int row = idx >> 3, c4 = idx & 7;
        float4 v = r[i];
        v.x = to_tf32(v.x); v.y = to_tf32(v.y); v.z = to_tf32(v.z); v.w = to_tf32(v.w);
        *reinterpret_cast<float4*>(sA + row * LDA + c4 * 4) = v;
    }
}

__device__ __forceinline__ void ldg_A_edge(float4 r[4],
                                           const float* __restrict__ nodes,
                                           const float* __restrict__ edges,
                                           const int* sidx, const int* ridx,
                                           long e0, long E, int chunk) {
    #pragma unroll
    for (int i = 0; i < 4; ++i) {
        const int idx = threadIdx.x + i * NTHR;
        const int row = idx >> 3, c4 = idx & 7;
        const float* src;
        if (chunk < 4)       src = nodes + (size_t)sidx[row] * D + chunk * 32;
        else if (chunk < 8)  src = nodes + (size_t)ridx[row] * D + (chunk - 4) * 32;
        else                 src = edges + (size_t)(e0 + row) * D + (chunk - 8) * 32;
        r[i] = (e0 + row < E) ? *reinterpret_cast<const float4*>(src + c4 * 4)
                              : make_float4(0.f, 0.f, 0.f, 0.f);
    }
}

__device__ __forceinline__ void ldg_A_node(float4 r[4],
                                           const float* __restrict__ nodes,
                                           long n0, long N, int chunk) {
    #pragma unroll
    for (int i = 0; i < 4; ++i) {
        const int idx = threadIdx.x + i * NTHR;
        const int row = idx >> 3, c4 = idx & 7;
        const long n = n0 + row;
        const float* src = (chunk < 4) ? nodes + (size_t)n * D + chunk * 32
                                       : g_agg + (size_t)n * D + (chunk - 4) * 32;
        r[i] = (n < N) ? *reinterpret_cast<const float4*>(src + c4 * 4)
                       : make_float4(0.f, 0.f, 0.f, 0.f);
    }
}

__device__ __forceinline__ void zero_acc(float acc[2][8][4]) {
    #pragma unroll
    for (int mf = 0; mf < 2; ++mf)
        #pragma unroll
        for (int nf = 0; nf < 8; ++nf)
            #pragma unroll
            for (int i = 0; i < 4; ++i) acc[mf][nf][i] = 0.f;
}

// Store acc(+bias1), relu, rna -> Hh; or acc(+bias2) -> Hh (no relu).
__device__ __forceinline__ void acc_to_H(float* Hh, float acc[2][8][4],
                                         const float* bias, int warp_m, int warp_n,
                                         int lane, bool relu_rna) {
    const int g = lane >> 2, t = lane & 3;
    #pragma unroll
    for (int mf = 0; mf < 2; ++mf) {
        const int r0 = warp_m * 32 + mf * 16 + g;
        #pragma unroll
        for (int nf = 0; nf < 8; ++nf) {
            const int col = warp_n * 64 + nf * 8 + 2 * t;
            float2 v0, v1;
            v0.x = acc[mf][nf][0] + bias[col];
            v0.y = acc[mf][nf][1] + bias[col + 1];
            v1.x = acc[mf][nf][2] + bias[col];
            v1.y = acc[mf][nf][3] + bias[col + 1];
            if (relu_rna) {
                v0.x = to_tf32(fmaxf(v0.x, 0.f)); v0.y = to_tf32(fmaxf(v0.y, 0.f));
                v1.x = to_tf32(fmaxf(v1.x, 0.f)); v1.y = to_tf32(fmaxf(v1.y, 0.f));
            }
            *reinterpret_cast<float2*>(&Hh[r0 * LDH + col]) = v0;
            *reinterpret_cast<float2*>(&Hh[(r0 + 8) * LDH + col]) = v1;
        }
    }
}

// =================== edge kernel ===================
__global__ void __launch_bounds__(NTHR, 2)
edge_kernel(const float* __restrict__ nodes, const float* __restrict__ edges,
            const int* __restrict__ senders, const int* __restrict__ receivers,
            const float* __restrict__ We1, const float* __restrict__ be1,
            const float* __restrict__ We2, const float* __restrict__ be2,
            float* __restrict__ out_edges, long E)
{
    extern __shared__ char smem_raw[];
    Smem& S = *reinterpret_cast<Smem*>(smem_raw);
    const long e0 = (long)blockIdx.x * BM;
    const int tid = threadIdx.x, lane = tid & 31;
    const int warp_m = (tid >> 5) & 1, warp_n = tid >> 6;

    if (tid < BM) { const long e = e0 + tid; S.sidx[tid] = (e < E) ? senders[e] : 0; }
    else          { const int r = tid - BM; const long e = e0 + r; S.ridx[r] = (e < E) ? receivers[e] : 0; }
    S.bias1[tid] = be1[tid];
    S.bias2[tid] = be2[tid];
    __syncthreads();

    float acc[2][8][4];
    zero_acc(acc);

    float4 ra[4], rb[8];

    // ---- GEMM1: [64,384] x [384,128], 12 K-chunks, double buffered ----
    ldg_A_edge(ra, nodes, edges, S.sidx, S.ridx, e0, E, 0);
    ldg_B(rb, We1, 0);
    sts_A(S.A[0], ra); sts_B(S.B[0], rb);
    __syncthreads();
    #pragma unroll 1
    for (int c = 0; c < 12; ++c) {
        const int cur = c & 1;
        if (c + 1 < 12) {
            ldg_A_edge(ra, nodes, edges, S.sidx, S.ridx, e0, E, c + 1);
            ldg_B(rb, We1, (c + 1) * BK);
        }
        mma_chunk<LDA>(S.A[cur], S.B[cur], warp_m, warp_n, lane, acc);
        if (c + 1 < 12) { sts_A(S.A[cur ^ 1], ra); sts_B(S.B[cur ^ 1], rb); }
        __syncthreads();
    }

    // h = rna(relu(acc + b1)) -> Hh ; prefetch W2 chunk0
    ldg_B(rb, We2, 0);
    acc_to_H(S.Hh, acc, S.bias1, warp_m, warp_n, lane, true);
    zero_acc(acc);
    sts_B(S.B[0], rb);
    __syncthreads();

    // ---- GEMM2: [64,128] x [128,128], 4 K-chunks ----
    #pragma unroll 1
    for (int c = 0; c < 4; ++c) {
        const int cur = c & 1;
        if (c + 1 < 4) ldg_B(rb, We2, (c + 1) * BK);
        mma_chunk<LDH>(S.Hh + c * BK, S.B[cur], warp_m, warp_n, lane, acc);
        if (c + 1 < 4) sts_B(S.B[cur ^ 1], rb);
        __syncthreads();
    }

    // y = acc + b2 -> Hh
    acc_to_H(S.Hh, acc, S.bias2, warp_m, warp_n, lane, false);
    __syncthreads();

    // new_edges = edges + y ; agg[recv] += y (vectorized red)
    #pragma unroll 1
    for (int i = 0; i < 16; ++i) {
        const int idx = tid + i * NTHR;            // 0..2047 over 64x32 float4
        const int row = idx >> 5, c4 = idx & 31;
        const long e = e0 + row;
        if (e < E) {
            const float4 ef = *reinterpret_cast<const float4*>(edges + (size_t)e * D + c4 * 4);
            const float4 y  = *reinterpret_cast<const float4*>(&S.Hh[row * LDH + c4 * 4]);
            float4 o;
            o.x = ef.x + y.x; o.y = ef.y + y.y; o.z = ef.z + y.z; o.w = ef.w + y.w;
            *reinterpret_cast<float4*>(out_edges + (size_t)e * D + c4 * 4) = o;
            float* dst = g_agg + (size_t)S.ridx[row] * D + c4 * 4;
            asm volatile("red.global.add.v4.f32 [%0], {%1,%2,%3,%4};"
                         :: "l"(dst), "f"(y.x), "f"(y.y), "f"(y.z), "f"(y.w) : "memory");
        }
    }
}

// =================== node kernel ===================
__global__ void __launch_bounds__(NTHR, 2)
node_kernel(const float* __restrict__ nodes,
            const float* __restrict__ Wn1, const float* __restrict__ bn1,
            const float* __restrict__ Wn2, const float* __restrict__ bn2,
            float* __restrict__ out_nodes, long N)
{
    extern __shared__ char smem_raw[];
    Smem& S = *reinterpret_cast<Smem*>(smem_raw);
    const long n0 = (long)blockIdx.x * BM;
    const int tid = threadIdx.x, lane = tid & 31;
    const int warp_m = (tid >> 5) & 1, warp_n = tid >> 6;

    S.bias1[tid] = bn1[tid];
    S.bias2[tid] = bn2[tid];
    __syncthreads();

    float acc[2][8][4];
    zero_acc(acc);

    float4 ra[4], rb[8];

    // ---- GEMM1: [64,256] x [256,128], 8 K-chunks ----
    ldg_A_node(ra, nodes, n0, N, 0);
    ldg_B(rb, Wn1, 0);
    sts_A(S.A[0], ra); sts_B(S.B[0], rb);
    __syncthreads();
    #pragma unroll 1
    for (int c = 0; c < 8; ++c) {
        const int cur = c & 1;
        if (c + 1 < 8) {
            ldg_A_node(ra, nodes, n0, N, c + 1);
            ldg_B(rb, Wn1, (c + 1) * BK);
        }
        mma_chunk<LDA>(S.A[cur], S.B[cur], warp_m, warp_n, lane, acc);
        if (c + 1 < 8) { sts_A(S.A[cur ^ 1], ra); sts_B(S.B[cur ^ 1], rb); }
        __syncthreads();
    }

    ldg_B(rb, Wn2, 0);
    acc_to_H(S.Hh, acc, S.bias1, warp_m, warp_n, lane, true);
    zero_acc(acc);
    sts_B(S.B[0], rb);
    __syncthreads();

    // ---- GEMM2: [64,128] x [128,128] ----
    #pragma unroll 1
    for (int c = 0; c < 4; ++c) {
        const int cur = c & 1;
        if (c + 1 < 4) ldg_B(rb, Wn2, (c + 1) * BK);
        mma_chunk<LDH>(S.Hh + c * BK, S.B[cur], warp_m, warp_n, lane, acc);
        if (c + 1 < 4) sts_B(S.B[cur ^ 1], rb);
        __syncthreads();
    }

    acc_to_H(S.Hh, acc, S.bias2, warp_m, warp_n, lane, false);
    __syncthreads();

    // new_nodes = nodes + y
    #pragma unroll 1
    for (int i = 0; i < 16; ++i) {
        const int idx = tid + i * NTHR;
        const int row = idx >> 5, c4 = idx & 31;
        const long n = n0 + row;
        if (n < N) {
            const float4 nf = *reinterpret_cast<const float4*>(nodes + (size_t)n * D + c4 * 4);
            const float4 y  = *reinterpret_cast<const float4*>(&S.Hh[row * LDH + c4 * 4]);
            float4 o;
            o.x = nf.x + y.x; o.y = nf.y + y.y; o.z = nf.z + y.z; o.w = nf.w + y.w;
            *reinterpret_cast<float4*>(out_nodes + (size_t)n * D + c4 * 4) = o;
        }
    }
}

// =================== zero the scatter scratch ===================
__global__ void zero_agg_kernel(long n4) {
    float4* p = reinterpret_cast<float4*>(g_agg);
    long i = (long)blockIdx.x * blockDim.x + threadIdx.x;
    const long stride = (long)gridDim.x * blockDim.x;
    const float4 z = make_float4(0.f, 0.f, 0.f, 0.f);
    for (; i < n4; i += stride) p[i] = z;
}

extern "C" void kernel_launch(void* const* d_in, const int* in_sizes, int n_in,
                              void* d_out, int out_size) {
    const float* nodes     = (const float*)d_in[0];
    const float* edges     = (const float*)d_in[1];
    const int*   senders   = (const int*)d_in[2];
    const int*   receivers = (const int*)d_in[3];
    const float* We1 = (const float*)d_in[4];
    const float* be1 = (const float*)d_in[5];
    const float* We2 = (const float*)d_in[6];
    const float* be2 = (const float*)d_in[7];
    const float* Wn1 = (const float*)d_in[8];
    const float* bn1 = (const float*)d_in[9];
    const float* Wn2 = (const float*)d_in[10];
    const float* bn2 = (const float*)d_in[11];

    const long N = (long)in_sizes[0] / D;
    const long E = (long)in_sizes[2];

    float* out_nodes = (float*)d_out;               // [N, D] first
    float* out_edges = out_nodes + (size_t)N * D;   // then [E, D]

    const int smem = (int)sizeof(Smem);
    cudaFuncSetAttribute(edge_kernel, cudaFuncAttributeMaxDynamicSharedMemorySize, smem);
    cudaFuncSetAttribute(node_kernel, cudaFuncAttributeMaxDynamicSharedMemorySize, smem);

    zero_agg_kernel<<<2048, 256>>>(N * D / 4);
    edge_kernel<<<(int)((E + BM - 1) / BM), NTHR, smem>>>(
        nodes, edges, senders, receivers, We1, be1, We2, be2, out_edges, E);
    node_kernel<<<(int)((N + BM - 1) / BM), NTHR, smem>>>(
        nodes, Wn1, bn1, Wn2, bn2, out_nodes, N);
}

// round 15
// speedup vs baseline: 1.0102x; 1.0010x over previous
#include <cuda_runtime.h>
#include <cstdint>

#define D 128
#define BM 64
#define BK 32
#define NTHR 128
#define LDA 36     // smem A leading dim (pad: (36r+c)%32 = (4r+c)%32 -> conflict-free frags)
#define LDH 132    // smem H leading dim (132%32==4, same property)
#define LDB 136    // smem B leading dim ((136k+n)%32 = (8k+n)%32 -> conflict-free frags)

#define MAX_NODES 100000

// scatter-sum scratch (51.2 MB) — __device__ global per allocation rules
__device__ __align__(16) float g_agg[(size_t)MAX_NODES * D];

struct Smem {
    float A[2][BM * LDA];   // 18432 B
    float B[2][BK * LDB];   // 34816 B
    float Hh[BM * LDH];     // 33792 B
    int   sidx[BM];
    int   ridx[BM];
    float bias1[D];
    float bias2[D];
};  // ~88.5 KB -> 2 blocks/SM

__device__ __forceinline__ float to_tf32(float x) {
    uint32_t u;
    asm("cvt.rna.tf32.f32 %0, %1;" : "=r"(u) : "f"(x));
    return __uint_as_float(u);
}

__device__ __forceinline__ void mma_tf32(float d[4], const uint32_t a[4], const uint32_t b[2]) {
    asm volatile(
        "mma.sync.aligned.m16n8k8.row.col.f32.tf32.tf32.f32 "
        "{%0,%1,%2,%3}, {%4,%5,%6,%7}, {%8,%9}, {%0,%1,%2,%3};"
        : "+f"(d[0]), "+f"(d[1]), "+f"(d[2]), "+f"(d[3])
        : "r"(a[0]), "r"(a[1]), "r"(a[2]), "r"(a[3]), "r"(b[0]), "r"(b[1]));
}

// One BK=32 K-chunk of mma for a 64x128 block tile. Warp tile = 32(m) x 64(n).
template <int LDA_T>
__device__ __forceinline__ void mma_chunk(const float* sA, const float* sB,
                                          int warp_m, int warp_n, int lane,
                                          float acc[2][8][4]) {
    const int g = lane >> 2, t = lane & 3;
    #pragma unroll
    for (int ks = 0; ks < 4; ++ks) {
        const int k = ks * 8;
        uint32_t a[2][4];
        #pragma unroll
        for (int mf = 0; mf < 2; ++mf) {
            const int r0 = warp_m * 32 + mf * 16 + g;
            a[mf][0] = __float_as_uint(sA[r0 * LDA_T + k + t]);
            a[mf][1] = __float_as_uint(sA[(r0 + 8) * LDA_T + k + t]);
            a[mf][2] = __float_as_uint(sA[r0 * LDA_T + k + t + 4]);
            a[mf][3] = __float_as_uint(sA[(r0 + 8) * LDA_T + k + t + 4]);
        }
        #pragma unroll
        for (int nf = 0; nf < 8; ++nf) {
            const int col = warp_n * 64 + nf * 8 + g;
            uint32_t b[2];
            b[0] = __float_as_uint(sB[(k + t) * LDB + col]);
            b[1] = __float_as_uint(sB[(k + t + 4) * LDB + col]);
            mma_tf32(acc[0][nf], a[0], b);
            mma_tf32(acc[1][nf], a[1], b);
        }
    }
}

// ---- global -> reg -> (rna tf32) -> smem staging ----

__device__ __forceinline__ void ldg_B(float4 r[8], const float* __restrict__ W, int k0) {
    #pragma unroll
    for (int i = 0; i < 8; ++i) {
        const int idx = threadIdx.x + i * NTHR;       // 0..1023 over 32x32 float4
        const int kr = idx >> 5, c4 = idx & 31;
        r[i] = *reinterpret_cast<const float4*>(W + (size_t)(k0 + kr) * D + c4 * 4);
    }
}

__device__ __forceinline__ void sts_B(float* sB, const float4 r[8]) {
    #pragma unroll
    for (int i = 0; i < 8; ++i) {
        const int idx = threadIdx.x + i * NTHR;
        const int kr = idx >> 5, c4 = idx & 31;
        float4 v = r[i];
        v.x = to_tf32(v.x); v.y = to_tf32(v.y); v.z = to_tf32(v.z); v.w = to_tf32(v.w);
        *reinterpret_cast<float4*>(sB + kr * LDB + c4 * 4) = v;
    }
}

__device__ __forceinline__ void sts_A(float* sA, const float4 r[4]) {
    #pragma unroll
    for (int i = 0; i < 4; ++i) {
        const int idx = threadIdx.x + i * NTHR;       // 0..511 over 64x8 float4
        const int row = idx >> 3, c4 = idx & 7;
        float4 v = r[i];
        v.x = to_tf32(v.x); v.y = to_tf32(v.y); v.z = to_tf32(v.z); v.w = to_tf32(v.w);
        *reinterpret_cast<float4*>(sA + row * LDA + c4 * 4) = v;
    }
}

__device__ __forceinline__ void ldg_A_edge(float4 r[4],
                                           const float* __restrict__ nodes,
                                           const float* __restrict__ edges,
                                           const int* sidx, const int* ridx,
                                           long e0, long E, int chunk) {
    #pragma unroll
    for (int i = 0; i < 4; ++i) {
        const int idx = threadIdx.x + i * NTHR;
        const int row = idx >> 3, c4 = idx & 7;
        const float* src;
        if (chunk < 4)       src = nodes + (size_t)sidx[row] * D + chunk * 32;
        else if (chunk < 8)  src = nodes + (size_t)ridx[row] * D + (chunk - 4) * 32;
        else                 src = edges + (size_t)(e0 + row) * D + (chunk - 8) * 32;
        r[i] = (e0 + row < E) ? *reinterpret_cast<const float4*>(src + c4 * 4)
                              : make_float4(0.f, 0.f, 0.f, 0.f);
    }
}

__device__ __forceinline__ void ldg_A_node(float4 r[4],
                                           const float* __restrict__ nodes,
                                           long n0, long N, int chunk) {
    #pragma unroll
    for (int i = 0; i < 4; ++i) {
        const int idx = threadIdx.x + i * NTHR;
        const int row = idx >> 3, c4 = idx & 7;
        const long n = n0 + row;
        const float* src = (chunk < 4) ? nodes + (size_t)n * D + chunk * 32
                                       : g_agg + (size_t)n * D + (chunk - 4) * 32;
        r[i] = (n < N) ? *reinterpret_cast<const float4*>(src + c4 * 4)
                       : make_float4(0.f, 0.f, 0.f, 0.f);
    }
}

__device__ __forceinline__ void zero_acc(float acc[2][8][4]) {
    #pragma unroll
    for (int mf = 0; mf < 2; ++mf)
        #pragma unroll
        for (int nf = 0; nf < 8; ++nf)
            #pragma unroll
            for (int i = 0; i < 4; ++i) acc[mf][nf][i] = 0.f;
}

// Store acc(+bias1), relu, rna -> Hh; or acc(+bias2) -> Hh (no relu).
__device__ __forceinline__ void acc_to_H(float* Hh, float acc[2][8][4],
                                         const float* bias, int warp_m, int warp_n,
                                         int lane, bool relu_rna) {
    const int g = lane >> 2, t = lane & 3;
    #pragma unroll
    for (int mf = 0; mf < 2; ++mf) {
        const int r0 = warp_m * 32 + mf * 16 + g;
        #pragma unroll
        for (int nf = 0; nf < 8; ++nf) {
            const int col = warp_n * 64 + nf * 8 + 2 * t;
            float2 v0, v1;
            v0.x = acc[mf][nf][0] + bias[col];
            v0.y = acc[mf][nf][1] + bias[col + 1];
            v1.x = acc[mf][nf][2] + bias[col];
            v1.y = acc[mf][nf][3] + bias[col + 1];
            if (relu_rna) {
                v0.x = to_tf32(fmaxf(v0.x, 0.f)); v0.y = to_tf32(fmaxf(v0.y, 0.f));
                v1.x = to_tf32(fmaxf(v1.x, 0.f)); v1.y = to_tf32(fmaxf(v1.y, 0.f));
            }
            *reinterpret_cast<float2*>(&Hh[r0 * LDH + col]) = v0;
            *reinterpret_cast<float2*>(&Hh[(r0 + 8) * LDH + col]) = v1;
        }
    }
}

// =================== edge kernel ===================
__global__ void __launch_bounds__(NTHR, 2)
edge_kernel(const float* __restrict__ nodes, const float* __restrict__ edges,
            const int* __restrict__ senders, const int* __restrict__ receivers,
            const float* __restrict__ We1, const float* __restrict__ be1,
            const float* __restrict__ We2, const float* __restrict__ be2,
            float* __restrict__ out_edges, long E)
{
    extern __shared__ char smem_raw[];
    Smem& S = *reinterpret_cast<Smem*>(smem_raw);
    const long e0 = (long)blockIdx.x * BM;
    const int tid = threadIdx.x, lane = tid & 31;
    const int warp_m = (tid >> 5) & 1, warp_n = tid >> 6;

    if (tid < BM) { const long e = e0 + tid; S.sidx[tid] = (e < E) ? senders[e] : 0; }
    else          { const int r = tid - BM; const long e = e0 + r; S.ridx[r] = (e < E) ? receivers[e] : 0; }
    S.bias1[tid] = be1[tid];
    S.bias2[tid] = be2[tid];
    __syncthreads();

    float acc[2][8][4];
    zero_acc(acc);

    float4 ra[4], rb[8];

    // ---- GEMM1: [64,384] x [384,128], 12 K-chunks, double buffered ----
    ldg_A_edge(ra, nodes, edges, S.sidx, S.ridx, e0, E, 0);
    ldg_B(rb, We1, 0);
    sts_A(S.A[0], ra); sts_B(S.B[0], rb);
    __syncthreads();
    #pragma unroll 1
    for (int c = 0; c < 12; ++c) {
        const int cur = c & 1;
        if (c + 1 < 12) {
            ldg_A_edge(ra, nodes, edges, S.sidx, S.ridx, e0, E, c + 1);
            ldg_B(rb, We1, (c + 1) * BK);
        }
        mma_chunk<LDA>(S.A[cur], S.B[cur], warp_m, warp_n, lane, acc);
        if (c + 1 < 12) { sts_A(S.A[cur ^ 1], ra); sts_B(S.B[cur ^ 1], rb); }
        __syncthreads();
    }

    // h = rna(relu(acc + b1)) -> Hh ; prefetch W2 chunk0
    ldg_B(rb, We2, 0);
    acc_to_H(S.Hh, acc, S.bias1, warp_m, warp_n, lane, true);
    zero_acc(acc);
    sts_B(S.B[0], rb);
    __syncthreads();

    // ---- GEMM2: [64,128] x [128,128], 4 K-chunks ----
    #pragma unroll 1
    for (int c = 0; c < 4; ++c) {
        const int cur = c & 1;
        if (c + 1 < 4) ldg_B(rb, We2, (c + 1) * BK);
        mma_chunk<LDH>(S.Hh + c * BK, S.B[cur], warp_m, warp_n, lane, acc);
        if (c + 1 < 4) sts_B(S.B[cur ^ 1], rb);
        __syncthreads();
    }

    // y = acc + b2 -> Hh
    acc_to_H(S.Hh, acc, S.bias2, warp_m, warp_n, lane, false);
    __syncthreads();

    // new_edges = edges + y ; agg[recv] += y (vectorized red)
    #pragma unroll 1
    for (int i = 0; i < 16; ++i) {
        const int idx = tid + i * NTHR;            // 0..2047 over 64x32 float4
        const int row = idx >> 5, c4 = idx & 31;
        const long e = e0 + row;
        if (e < E) {
            const float4 ef = *reinterpret_cast<const float4*>(edges + (size_t)e * D + c4 * 4);
            const float4 y  = *reinterpret_cast<const float4*>(&S.Hh[row * LDH + c4 * 4]);
            float4 o;
            o.x = ef.x + y.x; o.y = ef.y + y.y; o.z = ef.z + y.z; o.w = ef.w + y.w;
            *reinterpret_cast<float4*>(out_edges + (size_t)e * D + c4 * 4) = o;
            float* dst = g_agg + (size_t)S.ridx[row] * D + c4 * 4;
            asm volatile("red.global.add.v4.f32 [%0], {%1,%2,%3,%4};"
                         :: "l"(dst), "f"(y.x), "f"(y.y), "f"(y.z), "f"(y.w) : "memory");
        }
    }
}

// =================== node kernel ===================
__global__ void __launch_bounds__(NTHR, 2)
node_kernel(const float* __restrict__ nodes,
            const float* __restrict__ Wn1, const float* __restrict__ bn1,
            const float* __restrict__ Wn2, const float* __restrict__ bn2,
            float* __restrict__ out_nodes, long N)
{
    extern __shared__ char smem_raw[];
    Smem& S = *reinterpret_cast<Smem*>(smem_raw);
    const long n0 = (long)blockIdx.x * BM;
    const int tid = threadIdx.x, lane = tid & 31;
    const int warp_m = (tid >> 5) & 1, warp_n = tid >> 6;

    S.bias1[tid] = bn1[tid];
    S.bias2[tid] = bn2[tid];
    __syncthreads();

    float acc[2][8][4];
    zero_acc(acc);

    float4 ra[4], rb[8];

    // ---- GEMM1: [64,256] x [256,128], 8 K-chunks ----
    ldg_A_node(ra, nodes, n0, N, 0);
    ldg_B(rb, Wn1, 0);
    sts_A(S.A[0], ra); sts_B(S.B[0], rb);
    __syncthreads();
    #pragma unroll 1
    for (int c = 0; c < 8; ++c) {
        const int cur = c & 1;
        if (c + 1 < 8) {
            ldg_A_node(ra, nodes, n0, N, c + 1);
            ldg_B(rb, Wn1, (c + 1) * BK);
        }
        mma_chunk<LDA>(S.A[cur], S.B[cur], warp_m, warp_n, lane, acc);
        if (c + 1 < 8) { sts_A(S.A[cur ^ 1], ra); sts_B(S.B[cur ^ 1], rb); }
        __syncthreads();
    }

    ldg_B(rb, Wn2, 0);
    acc_to_H(S.Hh, acc, S.bias1, warp_m, warp_n, lane, true);
    zero_acc(acc);
    sts_B(S.B[0], rb);
    __syncthreads();

    // ---- GEMM2: [64,128] x [128,128] ----
    #pragma unroll 1
    for (int c = 0; c < 4; ++c) {
        const int cur = c & 1;
        if (c + 1 < 4) ldg_B(rb, Wn2, (c + 1) * BK);
        mma_chunk<LDH>(S.Hh + c * BK, S.B[cur], warp_m, warp_n, lane, acc);
        if (c + 1 < 4) sts_B(S.B[cur ^ 1], rb);
        __syncthreads();
    }

    acc_to_H(S.Hh, acc, S.bias2, warp_m, warp_n, lane, false);
    __syncthreads();

    // new_nodes = nodes + y
    #pragma unroll 1
    for (int i = 0; i < 16; ++i) {
        const int idx = tid + i * NTHR;
        const int row = idx >> 5, c4 = idx & 31;
        const long n = n0 + row;
        if (n < N) {
            const float4 nf = *reinterpret_cast<const float4*>(nodes + (size_t)n * D + c4 * 4);
            const float4 y  = *reinterpret_cast<const float4*>(&S.Hh[row * LDH + c4 * 4]);
            float4 o;
            o.x = nf.x + y.x; o.y = nf.y + y.y; o.z = nf.z + y.z; o.w = nf.w + y.w;
            *reinterpret_cast<float4*>(out_nodes + (size_t)n * D + c4 * 4) = o;
        }
    }
}

// =================== zero the scatter scratch ===================
__global__ void zero_agg_kernel(long n4) {
    float4* p = reinterpret_cast<float4*>(g_agg);
    long i = (long)blockIdx.x * blockDim.x + threadIdx.x;
    const long stride = (long)gridDim.x * blockDim.x;
    const float4 z = make_float4(0.f, 0.f, 0.f, 0.f);
    for (; i < n4; i += stride) p[i] = z;
}

extern "C" void kernel_launch(void* const* d_in, const int* in_sizes, int n_in,
                              void* d_out, int out_size) {
    const float* nodes     = (const float*)d_in[0];
    const float* edges     = (const float*)d_in[1];
    const int*   senders   = (const int*)d_in[2];
    const int*   receivers = (const int*)d_in[3];
    const float* We1 = (const float*)d_in[4];
    const float* be1 = (const float*)d_in[5];
    const float* We2 = (const float*)d_in[6];
    const float* be2 = (const float*)d_in[7];
    const float* Wn1 = (const float*)d_in[8];
    const float* bn1 = (const float*)d_in[9];
    const float* Wn2 = (const float*)d_in[10];
    const float* bn2 = (const float*)d_in[11];

    const long N = (long)in_sizes[0] / D;
    const long E = (long)in_sizes[2];

    float* out_nodes = (float*)d_out;               // [N, D] first
    float* out_edges = out_nodes + (size_t)N * D;   // then [E, D]

    const int smem = (int)sizeof(Smem);
    cudaFuncSetAttribute(edge_kernel, cudaFuncAttributeMaxDynamicSharedMemorySize, smem);
    cudaFuncSetAttribute(node_kernel, cudaFuncAttributeMaxDynamicSharedMemorySize, smem);

    zero_agg_kernel<<<2048, 256>>>(N * D / 4);
    edge_kernel<<<(int)((E + BM - 1) / BM), NTHR, smem>>>(
        nodes, edges, senders, receivers, We1, be1, We2, be2, out_edges, E);
    node_kernel<<<(int)((N + BM - 1) / BM), NTHR, smem>>>(
        nodes, Wn1, bn1, Wn2, bn2, out_nodes, N);
}

// round 16
// speedup vs baseline: 1.5416x; 1.5259x over previous
#include <cuda_runtime.h>
#include <cuda_fp16.h>
#include <cstdint>

#define D 128
#define BM 128
#define BK 32
#define NTHR 256
#define LDAH 40     // smem A leading dim in halves (80B rows: ldmatrix conflict-free, 16B aligned)
#define LDK  40     // smem Bt leading dim in halves
#define LDHH 136    // smem H (fp16) leading dim (272B rows: stride mod 128 = 16 -> conflict-free)
#define LDH32 132   // smem H (fp32) leading dim for final y

#define MAX_NODES 100000

// -------- device-global scratch (allocation rules) --------
__device__ __align__(16) float  g_agg[(size_t)MAX_NODES * D];       // scatter-sum, fp32
__device__ __align__(16) __half g_nodes16[(size_t)MAX_NODES * D];   // fp16 node feats
__device__ __align__(16) __half g_We1t[3 * D * D];  // [n=128][k=384]
__device__ __align__(16) __half g_We2t[D * D];      // [128][128]
__device__ __align__(16) __half g_Wn1t[2 * D * D];  // [128][256]
__device__ __align__(16) __half g_Wn2t[D * D];      // [128][128]

struct Smem {
    __half A[2][BM * LDAH];                               // 20480 B
    __half Bt[2][D * LDK];                                // 20480 B
    union { __half h[BM * LDHH]; float f[BM * LDH32]; } H; // 67584 B
    int   sidx[BM];
    int   ridx[BM];
    float bias1[D];
    float bias2[D];
};  // ~110.6 KB -> 2 blocks/SM

// -------- PTX helpers --------
__device__ __forceinline__ void ldsm_x4(uint32_t r[4], const void* p) {
    uint32_t addr = (uint32_t)__cvta_generic_to_shared(p);
    asm volatile("ldmatrix.sync.aligned.m8n8.x4.shared.b16 {%0,%1,%2,%3}, [%4];"
                 : "=r"(r[0]), "=r"(r[1]), "=r"(r[2]), "=r"(r[3]) : "r"(addr));
}

__device__ __forceinline__ void mma_f16(float d[4], const uint32_t a[4],
                                        uint32_t b0, uint32_t b1) {
    asm volatile(
        "mma.sync.aligned.m16n8k16.row.col.f32.f16.f16.f32 "
        "{%0,%1,%2,%3}, {%4,%5,%6,%7}, {%8,%9}, {%0,%1,%2,%3};"
        : "+f"(d[0]), "+f"(d[1]), "+f"(d[2]), "+f"(d[3])
        : "r"(a[0]), "r"(a[1]), "r"(a[2]), "r"(a[3]), "r"(b0), "r"(b1));
}

// One BK=32 K-chunk for a 128x128 block tile. Warp tile = 32(m) x 64(n).
// A: [row][k] fp16, LDA_T halves. Bt: [n][k] fp16, LDK halves.
template <int LDA_T>
__device__ __forceinline__ void mma_chunk(const __half* sA, const __half* sBt,
                                          int warp_m, int warp_n, int lane,
                                          float acc[2][8][4]) {
    const int l15 = lane & 15;
    const int ahi = (lane >> 4) * 8;
    const int bn  = (lane & 7) + ((lane >> 4) & 1) * 8;
    const int bk  = ((lane >> 3) & 1) * 8;
    #pragma unroll
    for (int kk = 0; kk < 2; ++kk) {
        const int k0 = kk * 16;
        uint32_t a[2][4];
        #pragma unroll
        for (int mf = 0; mf < 2; ++mf)
            ldsm_x4(a[mf], sA + (warp_m * 32 + mf * 16 + l15) * LDA_T + k0 + ahi);
        #pragma unroll
        for (int ng = 0; ng < 4; ++ng) {
            uint32_t b[4];
            ldsm_x4(b, sBt + (warp_n * 64 + ng * 16 + bn) * LDK + k0 + bk);
            mma_f16(acc[0][2 * ng],     a[0], b[0], b[1]);
            mma_f16(acc[1][2 * ng],     a[1], b[0], b[1]);
            mma_f16(acc[0][2 * ng + 1], a[0], b[2], b[3]);
            mma_f16(acc[1][2 * ng + 1], a[1], b[2], b[3]);
        }
    }
}

// -------- staging --------

// fp16 gather (node features) for edge kernel chunks 0-7
__device__ __forceinline__ void ldg_A16_gather(uint4 r[2], const int* sidx, const int* ridx,
                                               int chunk, int tid) {
    #pragma unroll
    for (int i = 0; i < 2; ++i) {
        const int idx = tid + i * NTHR;          // 0..511 over 128 rows x 4 uint4
        const int row = idx >> 2, c8 = idx & 3;
        const int node = (chunk < 4) ? sidx[row] : ridx[row];
        r[i] = *reinterpret_cast<const uint4*>(
            g_nodes16 + (size_t)node * D + (chunk & 3) * 32 + c8 * 8);
    }
}

// fp16 direct rows (node kernel chunks 0-3)
__device__ __forceinline__ void ldg_A16_node(uint4 r[2], long n0, long N, int chunk, int tid) {
    #pragma unroll
    for (int i = 0; i < 2; ++i) {
        const int idx = tid + i * NTHR;
        const int row = idx >> 2, c8 = idx & 3;
        const long n = n0 + row;
        r[i] = (n < N) ? *reinterpret_cast<const uint4*>(
                             g_nodes16 + (size_t)n * D + chunk * 32 + c8 * 8)
                       : make_uint4(0u, 0u, 0u, 0u);
    }
}

__device__ __forceinline__ void sts_A16(__half* sA, const uint4 r[2], int tid) {
    #pragma unroll
    for (int i = 0; i < 2; ++i) {
        const int idx = tid + i * NTHR;
        const int row = idx >> 2, c8 = idx & 3;
        *reinterpret_cast<uint4*>(sA + row * LDAH + c8 * 8) = r[i];
    }
}

// fp32 sources (edge features / agg)
__device__ __forceinline__ void ldg_A32_edge(float4 r[4], const float* __restrict__ edges,
                                             long e0, long E, int chunk, int tid) {
    #pragma unroll
    for (int i = 0; i < 4; ++i) {
        const int idx = tid + i * NTHR;          // 0..1023 over 128 rows x 8 float4
        const int row = idx >> 3, c4 = idx & 7;
        const long e = e0 + row;
        r[i] = (e < E) ? *reinterpret_cast<const float4*>(
                             edges + (size_t)e * D + (chunk - 8) * 32 + c4 * 4)
                       : make_float4(0.f, 0.f, 0.f, 0.f);
    }
}

__device__ __forceinline__ void ldg_A32_agg(float4 r[4], long n0, long N, int chunk, int tid) {
    #pragma unroll
    for (int i = 0; i < 4; ++i) {
        const int idx = tid + i * NTHR;
        const int row = idx >> 3, c4 = idx & 7;
        const long n = n0 + row;
        r[i] = (n < N) ? *reinterpret_cast<const float4*>(
                             g_agg + (size_t)n * D + (chunk - 4) * 32 + c4 * 4)
                       : make_float4(0.f, 0.f, 0.f, 0.f);
    }
}

__device__ __forceinline__ void sts_A32(__half* sA, const float4 r[4], int tid) {
    #pragma unroll
    for (int i = 0; i < 4; ++i) {
        const int idx = tid + i * NTHR;
        const int row = idx >> 3, c4 = idx & 7;
        const float4 v = r[i];
        __half2 h0 = __floats2half2_rn(v.x, v.y);
        __half2 h1 = __floats2half2_rn(v.z, v.w);
        __half* p = sA + row * LDAH + c4 * 4;
        *reinterpret_cast<__half2*>(p)     = h0;
        *reinterpret_cast<__half2*>(p + 2) = h1;
    }
}

// weights: pre-transposed fp16 [n=128][K]
__device__ __forceinline__ void ldg_B16(uint4 r[2], const __half* __restrict__ Wt,
                                        int K, int k0, int tid) {
    #pragma unroll
    for (int i = 0; i < 2; ++i) {
        const int idx = tid + i * NTHR;          // 0..511 over 128 n x 4 uint4
        const int n = idx >> 2, kq = idx & 3;
        r[i] = *reinterpret_cast<const uint4*>(Wt + (size_t)n * K + k0 + kq * 8);
    }
}

__device__ __forceinline__ void sts_B16(__half* sBt, const uint4 r[2], int tid) {
    #pragma unroll
    for (int i = 0; i < 2; ++i) {
        const int idx = tid + i * NTHR;
        const int n = idx >> 2, kq = idx & 3;
        *reinterpret_cast<uint4*>(sBt + n * LDK + kq * 8) = r[i];
    }
}

__device__ __forceinline__ void zero_acc(float acc[2][8][4]) {
    #pragma unroll
    for (int mf = 0; mf < 2; ++mf)
        #pragma unroll
        for (int nf = 0; nf < 8; ++nf)
            #pragma unroll
            for (int i = 0; i < 4; ++i) acc[mf][nf][i] = 0.f;
}

// hidden: relu(acc + b1) -> fp16 H
__device__ __forceinline__ void acc_to_Hh(__half* Hh, float acc[2][8][4], const float* bias,
                                          int warp_m, int warp_n, int lane) {
    const int g = lane >> 2, t = lane & 3;
    #pragma unroll
    for (int mf = 0; mf < 2; ++mf) {
        const int r0 = warp_m * 32 + mf * 16 + g;
        #pragma unroll
        for (int nf = 0; nf < 8; ++nf) {
            const int col = warp_n * 64 + nf * 8 + 2 * t;
            __half2 h0 = __floats2half2_rn(fmaxf(acc[mf][nf][0] + bias[col], 0.f),
                                           fmaxf(acc[mf][nf][1] + bias[col + 1], 0.f));
            __half2 h1 = __floats2half2_rn(fmaxf(acc[mf][nf][2] + bias[col], 0.f),
                                           fmaxf(acc[mf][nf][3] + bias[col + 1], 0.f));
            *reinterpret_cast<__half2*>(&Hh[r0 * LDHH + col])       = h0;
            *reinterpret_cast<__half2*>(&Hh[(r0 + 8) * LDHH + col]) = h1;
        }
    }
}

// final: y = acc + b2 -> fp32 H
__device__ __forceinline__ void acc_to_Hf(float* Hf, float acc[2][8][4], const float* bias,
                                          int warp_m, int warp_n, int lane) {
    const int g = lane >> 2, t = lane & 3;
    #pragma unroll
    for (int mf = 0; mf < 2; ++mf) {
        const int r0 = warp_m * 32 + mf * 16 + g;
        #pragma unroll
        for (int nf = 0; nf < 8; ++nf) {
            const int col = warp_n * 64 + nf * 8 + 2 * t;
            float2 v0, v1;
            v0.x = acc[mf][nf][0] + bias[col];
            v0.y = acc[mf][nf][1] + bias[col + 1];
            v1.x = acc[mf][nf][2] + bias[col];
            v1.y = acc[mf][nf][3] + bias[col + 1];
            *reinterpret_cast<float2*>(&Hf[r0 * LDH32 + col])       = v0;
            *reinterpret_cast<float2*>(&Hf[(r0 + 8) * LDH32 + col]) = v1;
        }
    }
}

// =================== edge kernel ===================
__global__ void __launch_bounds__(NTHR, 2)
edge_kernel(const float* __restrict__ edges,
            const int* __restrict__ senders, const int* __restrict__ receivers,
            const float* __restrict__ be1, const float* __restrict__ be2,
            float* __restrict__ out_edges, long E)
{
    extern __shared__ char smem_raw[];
    Smem& S = *reinterpret_cast<Smem*>(smem_raw);
    const long e0 = (long)blockIdx.x * BM;
    const int tid = threadIdx.x, lane = tid & 31, wid = tid >> 5;
    const int warp_m = wid & 3, warp_n = wid >> 2;

    if (tid < BM) {
        const long e = e0 + tid;
        S.sidx[tid] = (e < E) ? senders[e] : 0;
        S.bias1[tid] = be1[tid];
        S.bias2[tid] = be2[tid];
    } else {
        const int r = tid - BM;
        const long e = e0 + r;
        S.ridx[r] = (e < E) ? receivers[e] : 0;
    }
    __syncthreads();

    float acc[2][8][4];
    zero_acc(acc);
    uint4 ra16[2]; float4 ra32[4]; uint4 rb[2];

    // ---- GEMM1: [128,384] x [384,128], 12 chunks, double buffered ----
    ldg_A16_gather(ra16, S.sidx, S.ridx, 0, tid);
    ldg_B16(rb, g_We1t, 3 * D, 0, tid);
    sts_A16(S.A[0], ra16, tid);
    sts_B16(S.Bt[0], rb, tid);
    __syncthreads();
    #pragma unroll 1
    for (int c = 0; c < 12; ++c) {
        const int cur = c & 1, nx = c + 1;
        if (nx < 12) {
            if (nx < 8) ldg_A16_gather(ra16, S.sidx, S.ridx, nx, tid);
            else        ldg_A32_edge(ra32, edges, e0, E, nx, tid);
            ldg_B16(rb, g_We1t, 3 * D, nx * BK, tid);
        }
        mma_chunk<LDAH>(S.A[cur], S.Bt[cur], warp_m, warp_n, lane, acc);
        if (nx < 12) {
            if (nx < 8) sts_A16(S.A[cur ^ 1], ra16, tid);
            else        sts_A32(S.A[cur ^ 1], ra32, tid);
            sts_B16(S.Bt[cur ^ 1], rb, tid);
        }
        __syncthreads();
    }

    acc_to_Hh(S.H.h, acc, S.bias1, warp_m, warp_n, lane);
    zero_acc(acc);
    ldg_B16(rb, g_We2t, D, 0, tid);
    sts_B16(S.Bt[0], rb, tid);
    __syncthreads();

    // ---- GEMM2: [128,128] x [128,128], 4 chunks ----
    #pragma unroll 1
    for (int c = 0; c < 4; ++c) {
        const int cur = c & 1;
        if (c + 1 < 4) ldg_B16(rb, g_We2t, D, (c + 1) * BK, tid);
        mma_chunk<LDHH>(S.H.h + c * BK, S.Bt[cur], warp_m, warp_n, lane, acc);
        if (c + 1 < 4) sts_B16(S.Bt[cur ^ 1], rb, tid);
        __syncthreads();
    }

    acc_to_Hf(S.H.f, acc, S.bias2, warp_m, warp_n, lane);
    __syncthreads();

    // new_edges = edges + y ; agg[recv] += y
    #pragma unroll 1
    for (int i = 0; i < 16; ++i) {
        const int idx = tid + i * NTHR;          // 0..4095 over 128 rows x 32 float4
        const int row = idx >> 5, c4 = idx & 31;
        const long e = e0 + row;
        if (e < E) {
            const float4 ef = *reinterpret_cast<const float4*>(edges + (size_t)e * D + c4 * 4);
            const float4 y  = *reinterpret_cast<const float4*>(&S.H.f[row * LDH32 + c4 * 4]);
            float4 o;
            o.x = ef.x + y.x; o.y = ef.y + y.y; o.z = ef.z + y.z; o.w = ef.w + y.w;
            *reinterpret_cast<float4*>(out_edges + (size_t)e * D + c4 * 4) = o;
            float* dst = g_agg + (size_t)S.ridx[row] * D + c4 * 4;
            asm volatile("red.global.add.v4.f32 [%0], {%1,%2,%3,%4};"
                         :: "l"(dst), "f"(y.x), "f"(y.y), "f"(y.z), "f"(y.w) : "memory");
        }
    }
}

// =================== node kernel ===================
__global__ void __launch_bounds__(NTHR, 2)
node_kernel(const float* __restrict__ nodes,
            const float* __restrict__ bn1, const float* __restrict__ bn2,
            float* __restrict__ out_nodes, long N)
{
    extern __shared__ char smem_raw[];
    Smem& S = *reinterpret_cast<Smem*>(smem_raw);
    const long n0 = (long)blockIdx.x * BM;
    const int tid = threadIdx.x, lane = tid & 31, wid = tid >> 5;
    const int warp_m = wid & 3, warp_n = wid >> 2;

    if (tid < D) { S.bias1[tid] = bn1[tid]; S.bias2[tid] = bn2[tid]; }
    __syncthreads();

    float acc[2][8][4];
    zero_acc(acc);
    uint4 ra16[2]; float4 ra32[4]; uint4 rb[2];

    // ---- GEMM1: [128,256] x [256,128], 8 chunks ----
    ldg_A16_node(ra16, n0, N, 0, tid);
    ldg_B16(rb, g_Wn1t, 2 * D, 0, tid);
    sts_A16(S.A[0], ra16, tid);
    sts_B16(S.Bt[0], rb, tid);
    __syncthreads();
    #pragma unroll 1
    for (int c = 0; c < 8; ++c) {
        const int cur = c & 1, nx = c + 1;
        if (nx < 8) {
            if (nx < 4) ldg_A16_node(ra16, n0, N, nx, tid);
            else        ldg_A32_agg(ra32, n0, N, nx, tid);
            ldg_B16(rb, g_Wn1t, 2 * D, nx * BK, tid);
        }
        mma_chunk<LDAH>(S.A[cur], S.Bt[cur], warp_m, warp_n, lane, acc);
        if (nx < 8) {
            if (nx < 4) sts_A16(S.A[cur ^ 1], ra16, tid);
            else        sts_A32(S.A[cur ^ 1], ra32, tid);
            sts_B16(S.Bt[cur ^ 1], rb, tid);
        }
        __syncthreads();
    }

    acc_to_Hh(S.H.h, acc, S.bias1, warp_m, warp_n, lane);
    zero_acc(acc);
    ldg_B16(rb, g_Wn2t, D, 0, tid);
    sts_B16(S.Bt[0], rb, tid);
    __syncthreads();

    // ---- GEMM2: [128,128] x [128,128] ----
    #pragma unroll 1
    for (int c = 0; c < 4; ++c) {
        const int cur = c & 1;
        if (c + 1 < 4) ldg_B16(rb, g_Wn2t, D, (c + 1) * BK, tid);
        mma_chunk<LDHH>(S.H.h + c * BK, S.Bt[cur], warp_m, warp_n, lane, acc);
        if (c + 1 < 4) sts_B16(S.Bt[cur ^ 1], rb, tid);
        __syncthreads();
    }

    acc_to_Hf(S.H.f, acc, S.bias2, warp_m, warp_n, lane);
    __syncthreads();

    // new_nodes = nodes + y  (residual from ORIGINAL fp32 nodes)
    #pragma unroll 1
    for (int i = 0; i < 16; ++i) {
        const int idx = tid + i * NTHR;
        const int row = idx >> 5, c4 = idx & 31;
        const long n = n0 + row;
        if (n < N) {
            const float4 nf = *reinterpret_cast<const float4*>(nodes + (size_t)n * D + c4 * 4);
            const float4 y  = *reinterpret_cast<const float4*>(&S.H.f[row * LDH32 + c4 * 4]);
            float4 o;
            o.x = nf.x + y.x; o.y = nf.y + y.y; o.z = nf.z + y.z; o.w = nf.w + y.w;
            *reinterpret_cast<float4*>(out_nodes + (size_t)n * D + c4 * 4) = o;
        }
    }
}

// =================== prep kernels ===================
__global__ void zero_agg_kernel(long n4) {
    float4* p = reinterpret_cast<float4*>(g_agg);
    long i = (long)blockIdx.x * blockDim.x + threadIdx.x;
    const long stride = (long)gridDim.x * blockDim.x;
    const float4 z = make_float4(0.f, 0.f, 0.f, 0.f);
    for (; i < n4; i += stride) p[i] = z;
}

__global__ void convert_nodes_kernel(const float* __restrict__ nodes, long n4) {
    long i = (long)blockIdx.x * blockDim.x + threadIdx.x;
    const long stride = (long)gridDim.x * blockDim.x;
    const float4* src = reinterpret_cast<const float4*>(nodes);
    __half2* dst = reinterpret_cast<__half2*>(g_nodes16);
    for (; i < n4; i += stride) {
        const float4 v = src[i];
        dst[i * 2]     = __floats2half2_rn(v.x, v.y);
        dst[i * 2 + 1] = __floats2half2_rn(v.z, v.w);
    }
}

// W [K][128] fp32 -> Wt [128][K] fp16 (rn)
__global__ void transpose_w_kernel(const float* __restrict__ W, int which, int K) {
    __half* Wt = (which == 0) ? g_We1t : (which == 1) ? g_We2t
               : (which == 2) ? g_Wn1t : g_Wn2t;
    const int idx = blockIdx.x * blockDim.x + threadIdx.x;
    if (idx < K * D) {
        const int k = idx / D, n = idx % D;
        Wt[(size_t)n * K + k] = __float2half_rn(W[idx]);
    }
}

extern "C" void kernel_launch(void* const* d_in, const int* in_sizes, int n_in,
                              void* d_out, int out_size) {
    const float* nodes     = (const float*)d_in[0];
    const float* edges     = (const float*)d_in[1];
    const int*   senders   = (const int*)d_in[2];
    const int*   receivers = (const int*)d_in[3];
    const float* We1 = (const float*)d_in[4];
    const float* be1 = (const float*)d_in[5];
    const float* We2 = (const float*)d_in[6];
    const float* be2 = (const float*)d_in[7];
    const float* Wn1 = (const float*)d_in[8];
    const float* bn1 = (const float*)d_in[9];
    const float* Wn2 = (const float*)d_in[10];
    const float* bn2 = (const float*)d_in[11];

    const long N = (long)in_sizes[0] / D;
    const long E = (long)in_sizes[2];

    float* out_nodes = (float*)d_out;               // [N, D] first
    float* out_edges = out_nodes + (size_t)N * D;   // then [E, D]

    const int smem = (int)sizeof(Smem);
    cudaFuncSetAttribute(edge_kernel, cudaFuncAttributeMaxDynamicSharedMemorySize, smem);
    cudaFuncSetAttribute(node_kernel, cudaFuncAttributeMaxDynamicSharedMemorySize, smem);

    convert_nodes_kernel<<<1024, 256>>>(nodes, N * D / 4);
    transpose_w_kernel<<<(3 * D * D + 255) / 256, 256>>>(We1, 0, 3 * D);
    transpose_w_kernel<<<(D * D + 255) / 256, 256>>>(We2, 1, D);
    transpose_w_kernel<<<(2 * D * D + 255) / 256, 256>>>(Wn1, 2, 2 * D);
    transpose_w_kernel<<<(D * D + 255) / 256, 256>>>(Wn2, 3, D);
    zero_agg_kernel<<<2048, 256>>>(N * D / 4);

    edge_kernel<<<(int)((E + BM - 1) / BM), NTHR, smem>>>(
        edges, senders, receivers, be1, be2, out_edges, E);
    node_kernel<<<(int)((N + BM - 1) / BM), NTHR, smem>>>(
        nodes, bn1, bn2, out_nodes, N);
}

// round 17
// speedup vs baseline: 1.7745x; 1.1511x over previous
#include <cuda_runtime.h>
#include <cuda_fp16.h>
#include <cstdint>

#define D 128
#define BM 128
#define BK 32
#define NTHR 256
#define STAGES 3
#define LDAH 40     // smem A leading dim in halves (80B rows: ldmatrix conflict-free, 16B aligned)
#define LDK  40     // smem Bt leading dim in halves
#define LDHH 136    // smem H (fp16) leading dim (272B rows, conflict-free)

#define MAX_NODES 100000

// -------- device-global scratch (allocation rules) --------
__device__ __align__(16) float  g_agg[(size_t)MAX_NODES * D];       // scatter-sum, fp32
__device__ __align__(16) __half g_nodes16[(size_t)MAX_NODES * D];   // fp16 node feats
__device__ __align__(16) __half g_We1t[3 * D * D];  // [n=128][k=384]
__device__ __align__(16) __half g_We2t[D * D];      // [128][128]
__device__ __align__(16) __half g_Wn1t[2 * D * D];  // [128][256]
__device__ __align__(16) __half g_Wn2t[D * D];      // [128][128]

struct Smem {
    __half A[STAGES][BM * LDAH];   // 30720 B
    __half Bt[STAGES][D * LDK];    // 30720 B
    __half H[BM * LDHH];           // 34816 B
    int   sidx[BM];
    int   ridx[BM];
    float bias1[D];
    float bias2[D];
};  // 98304 B -> 2 blocks/SM

// -------- PTX helpers --------
__device__ __forceinline__ void cp16(void* smem, const void* gmem) {
    uint32_t s = (uint32_t)__cvta_generic_to_shared(smem);
    asm volatile("cp.async.cg.shared.global [%0], [%1], 16;" :: "r"(s), "l"(gmem));
}
__device__ __forceinline__ void cp_commit() {
    asm volatile("cp.async.commit_group;");
}
template <int N>
__device__ __forceinline__ void cp_wait() {
    asm volatile("cp.async.wait_group %0;" :: "n"(N));
}

__device__ __forceinline__ void ldsm_x4(uint32_t r[4], const void* p) {
    uint32_t addr = (uint32_t)__cvta_generic_to_shared(p);
    asm volatile("ldmatrix.sync.aligned.m8n8.x4.shared.b16 {%0,%1,%2,%3}, [%4];"
                 : "=r"(r[0]), "=r"(r[1]), "=r"(r[2]), "=r"(r[3]) : "r"(addr));
}

__device__ __forceinline__ void mma_f16(float d[4], const uint32_t a[4],
                                        uint32_t b0, uint32_t b1) {
    asm volatile(
        "mma.sync.aligned.m16n8k16.row.col.f32.f16.f16.f32 "
        "{%0,%1,%2,%3}, {%4,%5,%6,%7}, {%8,%9}, {%0,%1,%2,%3};"
        : "+f"(d[0]), "+f"(d[1]), "+f"(d[2]), "+f"(d[3])
        : "r"(a[0]), "r"(a[1]), "r"(a[2]), "r"(a[3]), "r"(b0), "r"(b1));
}

// One BK=32 K-chunk for a 128x128 block tile. Warp tile = 32(m) x 64(n).
template <int LDA_T>
__device__ __forceinline__ void mma_chunk(const __half* sA, const __half* sBt,
                                          int warp_m, int warp_n, int lane,
                                          float acc[2][8][4]) {
    const int l15 = lane & 15;
    const int ahi = (lane >> 4) * 8;
    const int bn  = (lane & 7) + ((lane >> 4) & 1) * 8;
    const int bk  = ((lane >> 3) & 1) * 8;
    #pragma unroll
    for (int kk = 0; kk < 2; ++kk) {
        const int k0 = kk * 16;
        uint32_t a[2][4];
        #pragma unroll
        for (int mf = 0; mf < 2; ++mf)
            ldsm_x4(a[mf], sA + (warp_m * 32 + mf * 16 + l15) * LDA_T + k0 + ahi);
        #pragma unroll
        for (int ng = 0; ng < 4; ++ng) {
            uint32_t b[4];
            ldsm_x4(b, sBt + (warp_n * 64 + ng * 16 + bn) * LDK + k0 + bk);
            mma_f16(acc[0][2 * ng],     a[0], b[0], b[1]);
            mma_f16(acc[1][2 * ng],     a[1], b[0], b[1]);
            mma_f16(acc[0][2 * ng + 1], a[0], b[2], b[3]);
            mma_f16(acc[1][2 * ng + 1], a[1], b[2], b[3]);
        }
    }
}

// -------- cp.async staging (fp16 sources) --------
__device__ __forceinline__ void cp_gatherA(__half* sA, const int* sidx, const int* ridx,
                                           int chunk, int tid) {
    #pragma unroll
    for (int i = 0; i < 2; ++i) {
        const int idx = tid + i * NTHR;          // 0..511 over 128 rows x 4 x 16B
        const int row = idx >> 2, c8 = idx & 3;
        const int node = (chunk < 4) ? sidx[row] : ridx[row];
        cp16(sA + row * LDAH + c8 * 8,
             g_nodes16 + (size_t)node * D + (chunk & 3) * 32 + c8 * 8);
    }
}

__device__ __forceinline__ void cp_nodeA(__half* sA, long n0, long N, int chunk, int tid) {
    #pragma unroll
    for (int i = 0; i < 2; ++i) {
        const int idx = tid + i * NTHR;
        const int row = idx >> 2, c8 = idx & 3;
        long n = n0 + row;
        if (n >= N) n = N - 1;   // clamp (results discarded)
        cp16(sA + row * LDAH + c8 * 8,
             g_nodes16 + (size_t)n * D + chunk * 32 + c8 * 8);
    }
}

__device__ __forceinline__ void cp_B(__half* sBt, const __half* __restrict__ Wt,
                                     int K, int k0, int tid) {
    #pragma unroll
    for (int i = 0; i < 2; ++i) {
        const int idx = tid + i * NTHR;          // 0..511 over 128 n x 4 x 16B
        const int n = idx >> 2, kq = idx & 3;
        cp16(sBt + n * LDK + kq * 8, Wt + (size_t)n * K + k0 + kq * 8);
    }
}

// -------- fp32 sources: reg path (ldg -> convert -> sts) --------
__device__ __forceinline__ void ldg_A32_edge(float4 r[4], const float* __restrict__ edges,
                                             long e0, long E, int chunk, int tid) {
    #pragma unroll
    for (int i = 0; i < 4; ++i) {
        const int idx = tid + i * NTHR;          // 0..1023 over 128 rows x 8 float4
        const int row = idx >> 3, c4 = idx & 7;
        const long e = e0 + row;
        r[i] = (e < E) ? *reinterpret_cast<const float4*>(
                             edges + (size_t)e * D + (chunk - 8) * 32 + c4 * 4)
                       : make_float4(0.f, 0.f, 0.f, 0.f);
    }
}

__device__ __forceinline__ void ldg_A32_agg(float4 r[4], long n0, long N, int chunk, int tid) {
    #pragma unroll
    for (int i = 0; i < 4; ++i) {
        const int idx = tid + i * NTHR;
        const int row = idx >> 3, c4 = idx & 7;
        const long n = n0 + row;
        r[i] = (n < N) ? *reinterpret_cast<const float4*>(
                             g_agg + (size_t)n * D + (chunk - 4) * 32 + c4 * 4)
                       : make_float4(0.f, 0.f, 0.f, 0.f);
    }
}

__device__ __forceinline__ void sts_A32(__half* sA, const float4 r[4], int tid) {
    #pragma unroll
    for (int i = 0; i < 4; ++i) {
        const int idx = tid + i * NTHR;
        const int row = idx >> 3, c4 = idx & 7;
        const float4 v = r[i];
        __half2 h0 = __floats2half2_rn(v.x, v.y);
        __half2 h1 = __floats2half2_rn(v.z, v.w);
        __half* p = sA + row * LDAH + c4 * 4;
        *reinterpret_cast<__half2*>(p)     = h0;
        *reinterpret_cast<__half2*>(p + 2) = h1;
    }
}

__device__ __forceinline__ void zero_acc(float acc[2][8][4]) {
    #pragma unroll
    for (int mf = 0; mf < 2; ++mf)
        #pragma unroll
        for (int nf = 0; nf < 8; ++nf)
            #pragma unroll
            for (int i = 0; i < 4; ++i) acc[mf][nf][i] = 0.f;
}

// hidden: relu(acc + b1) -> fp16 H
__device__ __forceinline__ void acc_to_Hh(__half* Hh, float acc[2][8][4], const float* bias,
                                          int warp_m, int warp_n, int lane) {
    const int g = lane >> 2, t = lane & 3;
    #pragma unroll
    for (int mf = 0; mf < 2; ++mf) {
        const int r0 = warp_m * 32 + mf * 16 + g;
        #pragma unroll
        for (int nf = 0; nf < 8; ++nf) {
            const int col = warp_n * 64 + nf * 8 + 2 * t;
            __half2 h0 = __floats2half2_rn(fmaxf(acc[mf][nf][0] + bias[col], 0.f),
                                           fmaxf(acc[mf][nf][1] + bias[col + 1], 0.f));
            __half2 h1 = __floats2half2_rn(fmaxf(acc[mf][nf][2] + bias[col], 0.f),
                                           fmaxf(acc[mf][nf][3] + bias[col + 1], 0.f));
            *reinterpret_cast<__half2*>(&Hh[r0 * LDHH + col])       = h0;
            *reinterpret_cast<__half2*>(&Hh[(r0 + 8) * LDHH + col]) = h1;
        }
    }
}

// =================== edge kernel ===================
__global__ void __launch_bounds__(NTHR, 2)
edge_kernel(const float* __restrict__ edges,
            const int* __restrict__ senders, const int* __restrict__ receivers,
            const float* __restrict__ be1, const float* __restrict__ be2,
            float* __restrict__ out_edges, long E)
{
    extern __shared__ char smem_raw[];
    Smem& S = *reinterpret_cast<Smem*>(smem_raw);
    const long e0 = (long)blockIdx.x * BM;
    const int tid = threadIdx.x, lane = tid & 31, wid = tid >> 5;
    const int warp_m = wid & 3, warp_n = wid >> 2;

    if (tid < BM) {
        const long e = e0 + tid;
        S.sidx[tid] = (e < E) ? senders[e] : 0;
        S.bias1[tid] = be1[tid];
        S.bias2[tid] = be2[tid];
    } else {
        const int r = tid - BM;
        const long e = e0 + r;
        S.ridx[r] = (e < E) ? receivers[e] : 0;
    }
    __syncthreads();

    float acc[2][8][4];
    zero_acc(acc);
    float4 ra32[4];

    // ---- GEMM1: [128,384] x [384,128], 12 chunks (0-7 fp16 gather, 8-11 fp32 edges) ----
    cp_gatherA(S.A[0], S.sidx, S.ridx, 0, tid);
    cp_B(S.Bt[0], g_We1t, 3 * D, 0, tid);
    cp_commit();
    cp_gatherA(S.A[1], S.sidx, S.ridx, 1, tid);
    cp_B(S.Bt[1], g_We1t, 3 * D, BK, tid);
    cp_commit();

    #pragma unroll 1
    for (int c = 0; c < 12; ++c) {
        if (c >= 8) sts_A32(S.A[c % STAGES], ra32, tid);   // loaded at iter c-1
        cp_wait<1>();
        __syncthreads();
        const int n2 = c + 2;
        if (n2 < 12) {
            if (n2 < 8) cp_gatherA(S.A[n2 % STAGES], S.sidx, S.ridx, n2, tid);
            cp_B(S.Bt[n2 % STAGES], g_We1t, 3 * D, n2 * BK, tid);
        }
        const int n1 = c + 1;
        if (n1 < 12 && n1 >= 8) ldg_A32_edge(ra32, edges, e0, E, n1, tid);
        cp_commit();
        mma_chunk<LDAH>(S.A[c % STAGES], S.Bt[c % STAGES], warp_m, warp_n, lane, acc);
    }
    __syncthreads();   // all warps done reading A/Bt stages

    acc_to_Hh(S.H, acc, S.bias1, warp_m, warp_n, lane);
    zero_acc(acc);

    // ---- GEMM2: [128,128] x [128,128], 4 chunks ----
    cp_B(S.Bt[0], g_We2t, D, 0, tid);   cp_commit();
    cp_B(S.Bt[1], g_We2t, D, BK, tid);  cp_commit();
    #pragma unroll 1
    for (int c = 0; c < 4; ++c) {
        cp_wait<1>();
        __syncthreads();   // at c==0 also publishes H
        if (c + 2 < 4) cp_B(S.Bt[(c + 2) % STAGES], g_We2t, D, (c + 2) * BK, tid);
        cp_commit();
        mma_chunk<LDHH>(S.H + c * BK, S.Bt[c % STAGES], warp_m, warp_n, lane, acc);
    }

    // ---- epilogue directly from accumulators ----
    {
        const int g = lane >> 2, t = lane & 3;
        #pragma unroll
        for (int mf = 0; mf < 2; ++mf) {
            #pragma unroll
            for (int half = 0; half < 2; ++half) {
                const int row = warp_m * 32 + mf * 16 + g + half * 8;
                const long e = e0 + row;
                if (e < E) {
                    const int rid = S.ridx[row];
                    #pragma unroll
                    for (int nf = 0; nf < 8; ++nf) {
                        const int col = warp_n * 64 + nf * 8 + 2 * t;
                        const float y0 = acc[mf][nf][2 * half]     + S.bias2[col];
                        const float y1 = acc[mf][nf][2 * half + 1] + S.bias2[col + 1];
                        const float2 ef = *reinterpret_cast<const float2*>(
                            edges + (size_t)e * D + col);
                        float2 o; o.x = ef.x + y0; o.y = ef.y + y1;
                        *reinterpret_cast<float2*>(out_edges + (size_t)e * D + col) = o;
                        float* dst = g_agg + (size_t)rid * D + col;
                        asm volatile("red.global.add.v2.f32 [%0], {%1,%2};"
                                     :: "l"(dst), "f"(y0), "f"(y1) : "memory");
                    }
                }
            }
        }
    }
}

// =================== node kernel ===================
__global__ void __launch_bounds__(NTHR, 2)
node_kernel(const float* __restrict__ nodes,
            const float* __restrict__ bn1, const float* __restrict__ bn2,
            float* __restrict__ out_nodes, long N)
{
    extern __shared__ char smem_raw[];
    Smem& S = *reinterpret_cast<Smem*>(smem_raw);
    const long n0 = (long)blockIdx.x * BM;
    const int tid = threadIdx.x, lane = tid & 31, wid = tid >> 5;
    const int warp_m = wid & 3, warp_n = wid >> 2;

    if (tid < D) { S.bias1[tid] = bn1[tid]; S.bias2[tid] = bn2[tid]; }
    __syncthreads();

    float acc[2][8][4];
    zero_acc(acc);
    float4 ra32[4];

    // ---- GEMM1: [128,256] x [256,128], 8 chunks (0-3 fp16 nodes, 4-7 fp32 agg) ----
    cp_nodeA(S.A[0], n0, N, 0, tid);
    cp_B(S.Bt[0], g_Wn1t, 2 * D, 0, tid);
    cp_commit();
    cp_nodeA(S.A[1], n0, N, 1, tid);
    cp_B(S.Bt[1], g_Wn1t, 2 * D, BK, tid);
    cp_commit();

    #pragma unroll 1
    for (int c = 0; c < 8; ++c) {
        if (c >= 4) sts_A32(S.A[c % STAGES], ra32, tid);
        cp_wait<1>();
        __syncthreads();
        const int n2 = c + 2;
        if (n2 < 8) {
            if (n2 < 4) cp_nodeA(S.A[n2 % STAGES], n0, N, n2, tid);
            cp_B(S.Bt[n2 % STAGES], g_Wn1t, 2 * D, n2 * BK, tid);
        }
        const int n1 = c + 1;
        if (n1 < 8 && n1 >= 4) ldg_A32_agg(ra32, n0, N, n1, tid);
        cp_commit();
        mma_chunk<LDAH>(S.A[c % STAGES], S.Bt[c % STAGES], warp_m, warp_n, lane, acc);
    }
    __syncthreads();

    acc_to_Hh(S.H, acc, S.bias1, warp_m, warp_n, lane);
    zero_acc(acc);

    // ---- GEMM2: [128,128] x [128,128] ----
    cp_B(S.Bt[0], g_Wn2t, D, 0, tid);   cp_commit();
    cp_B(S.Bt[1], g_Wn2t, D, BK, tid);  cp_commit();
    #pragma unroll 1
    for (int c = 0; c < 4; ++c) {
        cp_wait<1>();
        __syncthreads();
        if (c + 2 < 4) cp_B(S.Bt[(c + 2) % STAGES], g_Wn2t, D, (c + 2) * BK, tid);
        cp_commit();
        mma_chunk<LDHH>(S.H + c * BK, S.Bt[c % STAGES], warp_m, warp_n, lane, acc);
    }

    // ---- epilogue: new_nodes = nodes(fp32) + y ----
    {
        const int g = lane >> 2, t = lane & 3;
        #pragma unroll
        for (int mf = 0; mf < 2; ++mf) {
            #pragma unroll
            for (int half = 0; half < 2; ++half) {
                const int row = warp_m * 32 + mf * 16 + g + half * 8;
                const long n = n0 + row;
                if (n < N) {
                    #pragma unroll
                    for (int nf = 0; nf < 8; ++nf) {
                        const int col = warp_n * 64 + nf * 8 + 2 * t;
                        const float y0 = acc[mf][nf][2 * half]     + S.bias2[col];
                        const float y1 = acc[mf][nf][2 * half + 1] + S.bias2[col + 1];
                        const float2 nfv = *reinterpret_cast<const float2*>(
                            nodes + (size_t)n * D + col);
                        float2 o; o.x = nfv.x + y0; o.y = nfv.y + y1;
                        *reinterpret_cast<float2*>(out_nodes + (size_t)n * D + col) = o;
                    }
                }
            }
        }
    }
}

// =================== fused prep: zero agg + convert nodes + transpose weights ===================
__global__ void prep_kernel(const float* __restrict__ nodes,
                            const float* __restrict__ We1, const float* __restrict__ We2,
                            const float* __restrict__ Wn1, const float* __restrict__ Wn2,
                            long N)
{
    const long t1 = N * (D / 4);                 // zero agg, float4 granularity
    const long t2 = t1 + N * (D / 4);            // convert nodes, float4 granularity
    const long t3 = t2 + 7 * D * D;              // weights, scalar
    long i = (long)blockIdx.x * blockDim.x + threadIdx.x;
    const long stride = (long)gridDim.x * blockDim.x;
    for (; i < t3; i += stride) {
        if (i < t1) {
            reinterpret_cast<float4*>(g_agg)[i] = make_float4(0.f, 0.f, 0.f, 0.f);
        } else if (i < t2) {
            const long j = i - t1;
            const float4 v = reinterpret_cast<const float4*>(nodes)[j];
            __half2* dst = reinterpret_cast<__half2*>(g_nodes16) + j * 2;
            dst[0] = __floats2half2_rn(v.x, v.y);
            dst[1] = __floats2half2_rn(v.z, v.w);
        } else {
            long j = i - t2;   // 0 .. 7*128*128-1
            const float* W; __half* Wt; int K;
            if (j < 3 * D * D)        { W = We1; Wt = g_We1t; K = 3 * D; }
            else if (j < 4 * D * D)   { j -= 3 * D * D; W = We2; Wt = g_We2t; K = D; }
            else if (j < 6 * D * D)   { j -= 4 * D * D; W = Wn1; Wt = g_Wn1t; K = 2 * D; }
            else                      { j -= 6 * D * D; W = Wn2; Wt = g_Wn2t; K = D; }
            const int k = (int)(j / D), n = (int)(j % D);
            Wt[(size_t)n * K + k] = __float2half_rn(W[j]);
        }
    }
}

__global__ void nop_kernel() {}

extern "C" void kernel_launch(void* const* d_in, const int* in_sizes, int n_in,
                              void* d_out, int out_size) {
    const float* nodes     = (const float*)d_in[0];
    const float* edges     = (const float*)d_in[1];
    const int*   senders   = (const int*)d_in[2];
    const int*   receivers = (const int*)d_in[3];
    const float* We1 = (const float*)d_in[4];
    const float* be1 = (const float*)d_in[5];
    const float* We2 = (const float*)d_in[6];
    const float* be2 = (const float*)d_in[7];
    const float* Wn1 = (const float*)d_in[8];
    const float* bn1 = (const float*)d_in[9];
    const float* Wn2 = (const float*)d_in[10];
    const float* bn2 = (const float*)d_in[11];

    const long N = (long)in_sizes[0] / D;
    const long E = (long)in_sizes[2];

    float* out_nodes = (float*)d_out;               // [N, D] first
    float* out_edges = out_nodes + (size_t)N * D;   // then [E, D]

    const int smem = (int)sizeof(Smem);
    cudaFuncSetAttribute(edge_kernel, cudaFuncAttributeMaxDynamicSharedMemorySize, smem);
    cudaFuncSetAttribute(node_kernel, cudaFuncAttributeMaxDynamicSharedMemorySize, smem);

    prep_kernel<<<1536, 256>>>(nodes, We1, We2, Wn1, Wn2, N);
    edge_kernel<<<(int)((E + BM - 1) / BM), NTHR, smem>>>(
        edges, senders, receivers, be1, be2, out_edges, E);
    node_kernel<<<(int)((N + BM - 1) / BM), NTHR, smem>>>(
        nodes, bn1, bn2, out_nodes, N);
    nop_kernel<<<1, 32>>>();   // keeps launch count at 4/call so ncu -s 5 lands on edge_kernel
}